// round 15
// baseline (speedup 1.0000x reference)
#include <cuda_runtime.h>
#include <cstdint>

#define N_NODES 100000
#define N_EDGES 1600000
#define D_EDGE  50
#define SLOTS   64
#define E_SPLIT 655360                  // edges [0,E_SPLIT) -> scatter role
#define N_GATHER_EDGES (N_EDGES - E_SPLIT)

#define SC_BLOCKS ((E_SPLIT * 13 + 255) / 256)          // 33280
#define GA_BLOCKS ((N_NODES * 32 + 255) / 256)          // 12500
#define GROUP_SC 8
#define GROUP_GA 3
#define GROUPS 4167                                      // covers both roles
#define GRID (GROUPS * (GROUP_SC + GROUP_GA))            // 45837

__device__ int g_idx_is_i64;
__device__ int g_cnt[N_NODES];
__device__ int g_slot[(size_t)N_NODES * SLOTS];
__device__ int g_ovf_n;
__device__ int g_ovf[N_GATHER_EDGES > 0 ? N_GATHER_EDGES : 1];

__device__ __forceinline__ long long load_recv(const void* __restrict__ recv, int e) {
    return g_idx_is_i64 ? ((const long long*)recv)[e]
                        : (long long)((const int*)recv)[e];
}

// ---------------------------------------------------------------------------
// Kernel 1: init. Block 0 detects receivers dtype (first 2048 words as int64:
// true int64 indices all in [0,N_NODES); packed int32 pairs blow the range).
// All blocks zero the 20MB output (scatter needs a zeroed base) + counters.
// ---------------------------------------------------------------------------
__global__ void init_kernel(const void* __restrict__ recv,
                            float4* __restrict__ out4) {
    if (blockIdx.x == 0) {
        const long long* p64 = (const long long*)recv;
        int bad = 0;
        for (int i = threadIdx.x; i < 2048; i += blockDim.x) {
            long long v = p64[i];
            if (v < 0 || v >= N_NODES) bad = 1;
        }
        int any_bad = __syncthreads_or(bad);
        if (threadIdx.x == 0) { g_idx_is_i64 = any_bad ? 0 : 1; g_ovf_n = 0; }
    }
    const int n4 = N_NODES * D_EDGE / 4;
    const int stride = gridDim.x * blockDim.x;
    for (int i = blockIdx.x * blockDim.x + threadIdx.x; i < n4; i += stride)
        out4[i] = make_float4(0.f, 0.f, 0.f, 0.f);
    for (int i = blockIdx.x * blockDim.x + threadIdx.x; i < N_NODES; i += stride)
        g_cnt[i] = 0;
}

// ---------------------------------------------------------------------------
// Kernel 2: build slot lists for the GATHER half only (edges [E_SPLIT, N)).
// 2 independent edges per thread to overlap ATOMG result latency.
// ---------------------------------------------------------------------------
__global__ void build_kernel(const void* __restrict__ recv) {
    const int T = blockDim.x;
    const int base = E_SPLIT + blockIdx.x * T * 2 + threadIdx.x;
#pragma unroll
    for (int k = 0; k < 2; k++) {
        const int e = base + k * T;
        if (e >= N_EDGES) continue;
        long long r = load_recv(recv, e);
        if ((unsigned long long)r >= (unsigned long long)N_NODES) continue;
        int pos = atomicAdd(&g_cnt[(int)r], 1);
        if (pos < SLOTS) g_slot[(size_t)r * SLOTS + pos] = e;
        else             g_ovf[atomicAdd(&g_ovf_n, 1)] = e;
    }
}

// ---------------------------------------------------------------------------
// Kernel 3: FUSED scatter+gather. Blocks are interleaved 8:3 into two roles
// that bottleneck on different units and run concurrently:
//   scatter role: edges [0, E_SPLIT), R10-style parity-phased red.v4/v2
//                 (sequential reads; L2 f32-RMW ALU bound)
//   gather role:  one warp per node, slot lists from edges [E_SPLIT, N),
//                 register accumulation (random reads; DRAM bound), partial
//                 added with 25 red.v2 per node.
// ---------------------------------------------------------------------------
__global__ void fused_kernel(const float* __restrict__ edges,
                             const void* __restrict__ recv,
                             float* __restrict__ out) {
    const int grp = blockIdx.x / (GROUP_SC + GROUP_GA);
    const int pos = blockIdx.x % (GROUP_SC + GROUP_GA);

    if (pos < GROUP_SC) {
        // ------------------ scatter role ------------------
        const int sblk = grp * GROUP_SC + pos;
        if (sblk >= SC_BLOCKS) return;
        const int idx = sblk * 256 + threadIdx.x;
        if (idx >= E_SPLIT * 13) return;
        const int e = idx / 13;
        const int c = idx - e * 13;

        long long r = load_recv(recv, e);
        if ((unsigned long long)r >= (unsigned long long)N_NODES) return;

        const float* row = edges + (size_t)e * D_EDGE;
        float* dst = out + (size_t)r * D_EDGE;
        const int odd = (int)(r & 1);

        if (c < 12) {
            const int off = 4 * c + 2 * odd;
            float2 a = *reinterpret_cast<const float2*>(row + off);
            float2 b = *reinterpret_cast<const float2*>(row + off + 2);
            asm volatile("red.global.add.v4.f32 [%0], {%1, %2, %3, %4};"
                         :: "l"(dst + off), "f"(a.x), "f"(a.y), "f"(b.x), "f"(b.y)
                         : "memory");
        } else {
            const int off = odd ? 0 : 48;
            float2 a = *reinterpret_cast<const float2*>(row + off);
            asm volatile("red.global.add.v2.f32 [%0], {%1, %2};"
                         :: "l"(dst + off), "f"(a.x), "f"(a.y)
                         : "memory");
        }
    } else {
        // ------------------ gather role ------------------
        const int gblk = grp * GROUP_GA + (pos - GROUP_SC);
        if (gblk >= GA_BLOCKS) return;
        const int warp = gblk * 8 + (threadIdx.x >> 5);
        const int lane = threadIdx.x & 31;
        if (warp >= N_NODES) return;

        const int cnt_raw = g_cnt[warp];
        const int cnt = (cnt_raw < SLOTS) ? cnt_raw : SLOTS;

        const int* slots = g_slot + (size_t)warp * SLOTS;
        const int e_lo = (lane < cnt) ? slots[lane] : 0;
        const int e_hi = (32 + lane < cnt) ? slots[32 + lane] : 0;

        const bool act = (lane < 25);
        const int d = 2 * lane;

        float2 a0 = make_float2(0.f, 0.f), a1 = make_float2(0.f, 0.f);
        float2 a2 = make_float2(0.f, 0.f), a3 = make_float2(0.f, 0.f);

        int j = 0;
        for (; j + 4 <= cnt; j += 4) {
            int e0 = __shfl_sync(0xffffffffu, (j + 0 < 32) ? e_lo : e_hi, (j + 0) & 31);
            int e1 = __shfl_sync(0xffffffffu, (j + 1 < 32) ? e_lo : e_hi, (j + 1) & 31);
            int e2 = __shfl_sync(0xffffffffu, (j + 2 < 32) ? e_lo : e_hi, (j + 2) & 31);
            int e3 = __shfl_sync(0xffffffffu, (j + 3 < 32) ? e_lo : e_hi, (j + 3) & 31);
            if (act) {
                float2 v0 = *reinterpret_cast<const float2*>(edges + (size_t)e0 * D_EDGE + d);
                float2 v1 = *reinterpret_cast<const float2*>(edges + (size_t)e1 * D_EDGE + d);
                float2 v2 = *reinterpret_cast<const float2*>(edges + (size_t)e2 * D_EDGE + d);
                float2 v3 = *reinterpret_cast<const float2*>(edges + (size_t)e3 * D_EDGE + d);
                a0.x += v0.x; a0.y += v0.y;
                a1.x += v1.x; a1.y += v1.y;
                a2.x += v2.x; a2.y += v2.y;
                a3.x += v3.x; a3.y += v3.y;
            }
        }
        for (; j < cnt; j++) {
            int e = __shfl_sync(0xffffffffu, (j < 32) ? e_lo : e_hi, j & 31);
            if (act) {
                float2 v = *reinterpret_cast<const float2*>(edges + (size_t)e * D_EDGE + d);
                a0.x += v.x; a0.y += v.y;
            }
        }

        // fused overflow fixup (expected empty; only overflowing nodes scan)
        if (cnt_raw > SLOTS) {
            const int n = g_ovf_n;
            for (int o = 0; o < n; o++) {
                int e = g_ovf[o];
                if ((int)load_recv(recv, e) == warp && act) {
                    float2 v = *reinterpret_cast<const float2*>(edges + (size_t)e * D_EDGE + d);
                    a0.x += v.x; a0.y += v.y;
                }
            }
        }

        if (act) {
            float sx = (a0.x + a1.x) + (a2.x + a3.x);
            float sy = (a0.y + a1.y) + (a2.y + a3.y);
            // skip the red entirely for all-zero partials (empty gather list)
            if (cnt_raw > 0) {
                asm volatile("red.global.add.v2.f32 [%0], {%1, %2};"
                             :: "l"(out + (size_t)warp * D_EDGE + d), "f"(sx), "f"(sy)
                             : "memory");
            }
        }
    }
}

extern "C" void kernel_launch(void* const* d_in, const int* in_sizes, int n_in,
                              void* d_out, int out_size) {
    // Identify inputs by element count (robust to ordering):
    //   nodes: 800,000 f32 (unused) | edges: 80,000,000 f32 | receivers: 1,600,000
    const float* edges = nullptr;
    const void* receivers = nullptr;
    for (int i = 0; i < n_in; i++) {
        if (in_sizes[i] == N_EDGES * D_EDGE) {
            edges = (const float*)d_in[i];
        } else if (in_sizes[i] == N_EDGES) {
            receivers = d_in[i];
        }
    }
    float* out = (float*)d_out;

    const int T = 256;

    // 1) detect dtype + zero output & counters
    init_kernel<<<2048, T>>>(receivers, (float4*)out);

    // 2) build slot lists for gather-half edges (2-way ILP)
    build_kernel<<<(N_GATHER_EDGES + T * 2 - 1) / (T * 2), T>>>(receivers);

    // 3) fused concurrent scatter + gather
    fused_kernel<<<GRID, T>>>(edges, receivers, out);
}

// round 16
// speedup vs baseline: 1.0936x; 1.0936x over previous
#include <cuda_runtime.h>
#include <cstdint>

#define N_NODES 100000
#define N_EDGES 1600000
#define D_EDGE  50
#define SLOTS   64            // fixed eid slots per node (binomial max degree ~40)
#define NPB     10            // nodes per block (10 groups of 25 threads)

// 1 if receivers buffer really holds int64, 0 if int32 (harness downcasts).
__device__ int g_idx_is_i64;

__device__ int g_cnt[N_NODES];
__device__ int g_slot[(size_t)N_NODES * SLOTS];  // 25.6MB
__device__ int g_ovf_n;                          // overflow count (expected 0)
__device__ int g_ovf[N_EDGES];

__device__ __forceinline__ long long load_recv(const void* __restrict__ recv, int e) {
    return g_idx_is_i64 ? ((const long long*)recv)[e]
                        : (long long)((const int*)recv)[e];
}

// ---------------------------------------------------------------------------
// Kernel 1: init. Block 0 detects receivers dtype (first 2048 words as int64:
// true int64 indices all lie in [0,N_NODES); packed int32 pairs blow the
// range w.p. ~1). All blocks zero counters. No output zeroing needed — the
// gather writes every row.
// ---------------------------------------------------------------------------
__global__ void init_kernel(const void* __restrict__ recv) {
    if (blockIdx.x == 0) {
        const long long* p64 = (const long long*)recv;
        int bad = 0;
        for (int i = threadIdx.x; i < 2048; i += blockDim.x) {
            long long v = p64[i];
            if (v < 0 || v >= N_NODES) bad = 1;
        }
        int any_bad = __syncthreads_or(bad);
        if (threadIdx.x == 0) { g_idx_is_i64 = any_bad ? 0 : 1; g_ovf_n = 0; }
    }
    for (int i = blockIdx.x * blockDim.x + threadIdx.x; i < N_NODES;
         i += gridDim.x * blockDim.x) {
        g_cnt[i] = 0;
    }
}

// ---------------------------------------------------------------------------
// Kernel 2: build slot lists, 4 independent edges per thread so the
// atomicAdd(result)->store chains overlap (ATOMG result latency ~318 cyc).
// ---------------------------------------------------------------------------
__global__ void build_kernel(const void* __restrict__ recv) {
    const int T = blockDim.x;
    const int base = blockIdx.x * T * 4 + threadIdx.x;

    int e[4], r[4], pos[4];
    bool ok[4];
#pragma unroll
    for (int k = 0; k < 4; k++) {
        e[k] = base + k * T;
        ok[k] = (e[k] < N_EDGES);
        if (ok[k]) {
            long long rr = load_recv(recv, e[k]);
            ok[k] = ((unsigned long long)rr < (unsigned long long)N_NODES);
            r[k] = (int)rr;
        }
    }
#pragma unroll
    for (int k = 0; k < 4; k++) {
        if (ok[k]) pos[k] = atomicAdd(&g_cnt[r[k]], 1);
    }
#pragma unroll
    for (int k = 0; k < 4; k++) {
        if (!ok[k]) continue;
        if (pos[k] < SLOTS) g_slot[(size_t)r[k] * SLOTS + pos[k]] = e[k];
        else                g_ovf[atomicAdd(&g_ovf_n, 1)] = e[k];
    }
}

// ---------------------------------------------------------------------------
// Kernel 3: gather, 25-thread groups (10 nodes per 256-thread block).
// Unlike the warp-per-node layout (7/32 lanes idle = 22% wasted load issue),
// every participating thread owns a real float2 dim-pair. Eids are staged in
// SMEM; all 25 threads of a group read the same word (broadcast, conflict-
// free). Edge rows are streamed with __ldcs (read exactly once -> keep L2
// clean). 4-way unroll for MLP. Overflow fixup fused (expected no-op).
// Writes every output row exactly once (zeros for empty nodes).
// ---------------------------------------------------------------------------
__global__ void gather_kernel(const float* __restrict__ edges,
                              const void* __restrict__ recv,
                              float* __restrict__ out) {
    __shared__ int s_eid[NPB][SLOTS];
    __shared__ int s_cnt[NPB];

    const int tid = threadIdx.x;
    const int node_base = blockIdx.x * NPB;

    if (tid < NPB) {
        const int node = node_base + tid;
        s_cnt[tid] = (node < N_NODES) ? g_cnt[node] : 0;
    }
    // stage slot lines (coalesced 256B per node; garbage past cnt is harmless)
    for (int i = tid; i < NPB * SLOTS; i += blockDim.x) {
        const int g = i >> 6;          // / SLOTS
        const int s = i & (SLOTS - 1);
        const int node = node_base + g;
        if (node < N_NODES) s_eid[g][s] = g_slot[(size_t)node * SLOTS + s];
    }
    __syncthreads();

    const int group = tid / 25;
    const int gl = tid - group * 25;
    if (group >= NPB) return;
    const int node = node_base + group;
    if (node >= N_NODES) return;

    const int cnt_raw = s_cnt[group];
    const int cnt = (cnt_raw < SLOTS) ? cnt_raw : SLOTS;
    const int d = 2 * gl;

    float2 a0 = make_float2(0.f, 0.f), a1 = make_float2(0.f, 0.f);
    float2 a2 = make_float2(0.f, 0.f), a3 = make_float2(0.f, 0.f);

    int j = 0;
    for (; j + 4 <= cnt; j += 4) {
        const int e0 = s_eid[group][j + 0];
        const int e1 = s_eid[group][j + 1];
        const int e2 = s_eid[group][j + 2];
        const int e3 = s_eid[group][j + 3];
        float2 v0 = __ldcs(reinterpret_cast<const float2*>(edges + (size_t)e0 * D_EDGE + d));
        float2 v1 = __ldcs(reinterpret_cast<const float2*>(edges + (size_t)e1 * D_EDGE + d));
        float2 v2 = __ldcs(reinterpret_cast<const float2*>(edges + (size_t)e2 * D_EDGE + d));
        float2 v3 = __ldcs(reinterpret_cast<const float2*>(edges + (size_t)e3 * D_EDGE + d));
        a0.x += v0.x; a0.y += v0.y;
        a1.x += v1.x; a1.y += v1.y;
        a2.x += v2.x; a2.y += v2.y;
        a3.x += v3.x; a3.y += v3.y;
    }
    for (; j < cnt; j++) {
        const int e = s_eid[group][j];
        float2 v = __ldcs(reinterpret_cast<const float2*>(edges + (size_t)e * D_EDGE + d));
        a0.x += v.x; a0.y += v.y;
    }

    // fused overflow fixup: only nodes that actually overflowed scan the list
    if (cnt_raw > SLOTS) {
        const int n = g_ovf_n;
        for (int o = 0; o < n; o++) {
            const int e = g_ovf[o];
            if ((int)load_recv(recv, e) == node) {
                float2 v = *reinterpret_cast<const float2*>(edges + (size_t)e * D_EDGE + d);
                a0.x += v.x; a0.y += v.y;
            }
        }
    }

    float2 r = make_float2((a0.x + a1.x) + (a2.x + a3.x),
                           (a0.y + a1.y) + (a2.y + a3.y));
    *reinterpret_cast<float2*>(out + (size_t)node * D_EDGE + d) = r;
}

extern "C" void kernel_launch(void* const* d_in, const int* in_sizes, int n_in,
                              void* d_out, int out_size) {
    // Identify inputs by element count (robust to ordering):
    //   nodes: 800,000 f32 (unused) | edges: 80,000,000 f32 | receivers: 1,600,000
    const float* edges = nullptr;
    const void* receivers = nullptr;
    for (int i = 0; i < n_in; i++) {
        if (in_sizes[i] == N_EDGES * D_EDGE) {
            edges = (const float*)d_in[i];
        } else if (in_sizes[i] == N_EDGES) {
            receivers = d_in[i];
        }
    }
    float* out = (float*)d_out;

    const int T = 256;

    // 1) detect dtype + zero counters
    init_kernel<<<392, T>>>(receivers);

    // 2) build per-node slot lists (4 edges/thread for atomic-latency ILP)
    build_kernel<<<(N_EDGES + T * 4 - 1) / (T * 4), T>>>(receivers);

    // 3) gather: 10 nodes per block, 25 threads per node, fused overflow
    gather_kernel<<<(N_NODES + NPB - 1) / NPB, T>>>(edges, receivers, out);
}